// round 1
// baseline (speedup 1.0000x reference)
#include <cuda_runtime.h>
#include <math.h>

// Problem constants
#define BATCH 4
#define CDIM 384
#define HDIM 128
#define WDIM 128
#define HW 16384            // 128*128
#define HEADS 8
#define CH 48               // CDIM / HEADS
#define NPLANE (BATCH*CDIM) // 1536 (b,c) planes / rows
#define NELEM (BATCH*CDIM*HW)

// Scratch (static device allocations — no cudaMalloc allowed)
__device__ float g_bufA[NELEM];
__device__ float g_bufB[NELEM];
__device__ float g_bufC[NELEM];
__device__ float g_bufD[NELEM];
__device__ float g_norms[2 * NPLANE];          // [0..1535] q-norms, [1536..] k-norms
__device__ float g_gpart[16 * 32 * CH * CH];   // 16 K-splits × 32 (b,h) × 48×48
__device__ float g_attn[32 * CH * CH];

// ---------------------------------------------------------------------------
// SGEMM: O[b] = A(MxK) @ X[b](KxN), M=384, K=384, N=16384, per batch z.
// A row-major with leading dim lda (384 for plain weights, 768 for w_qcat).
// accflag=1 -> O += A@X (second half of the concat-1x1 conv).
// 128x128 block tile, BK=16, 8x8 per thread (split-raked 4+4 layout).
// ---------------------------------------------------------------------------
__global__ __launch_bounds__(256) void sgemm_k(
    const float* __restrict__ A, int lda,
    const float* __restrict__ X, float* __restrict__ O, int accflag)
{
    const int N = HW;
    const int K = CDIM;
    const float* Xb = X + (size_t)blockIdx.z * CDIM * HW;
    float*       Ob = O + (size_t)blockIdx.z * CDIM * HW;
    const int mBase = blockIdx.y * 128;
    const int nBase = blockIdx.x * 128;

    __shared__ float As[16][128];
    __shared__ float Bs[16][128];

    const int tid = threadIdx.x;
    const int tr = tid >> 4;    // 0..15
    const int tc = tid & 15;    // 0..15

    float cr[8][8];
#pragma unroll
    for (int i = 0; i < 8; i++)
#pragma unroll
        for (int j = 0; j < 8; j++) cr[i][j] = 0.f;

    for (int k0 = 0; k0 < K; k0 += 16) {
        // Load A tile 128x16 (row-major), store transposed into As[k][m]
#pragma unroll
        for (int l = 0; l < 2; l++) {
            int f  = tid + l * 256;        // 0..511 float4 slots
            int m  = f >> 2;               // 0..127
            int kq = (f & 3) << 2;         // 0,4,8,12
            float4 va = *reinterpret_cast<const float4*>(
                &A[(size_t)(mBase + m) * lda + k0 + kq]);
            As[kq + 0][m] = va.x;
            As[kq + 1][m] = va.y;
            As[kq + 2][m] = va.z;
            As[kq + 3][m] = va.w;
        }
        // Load B tile 16x128 (rows contiguous)
#pragma unroll
        for (int l = 0; l < 2; l++) {
            int f  = tid + l * 256;
            int kk = f >> 5;               // 0..15
            int nq = (f & 31) << 2;        // 0..124
            *reinterpret_cast<float4*>(&Bs[kk][nq]) =
                *reinterpret_cast<const float4*>(
                    &Xb[(size_t)(k0 + kk) * N + nBase + nq]);
        }
        __syncthreads();

#pragma unroll
        for (int kk = 0; kk < 16; kk++) {
            float ar[8], br[8];
            *reinterpret_cast<float4*>(&ar[0]) =
                *reinterpret_cast<const float4*>(&As[kk][tr * 4]);
            *reinterpret_cast<float4*>(&ar[4]) =
                *reinterpret_cast<const float4*>(&As[kk][64 + tr * 4]);
            *reinterpret_cast<float4*>(&br[0]) =
                *reinterpret_cast<const float4*>(&Bs[kk][tc * 4]);
            *reinterpret_cast<float4*>(&br[4]) =
                *reinterpret_cast<const float4*>(&Bs[kk][64 + tc * 4]);
#pragma unroll
            for (int i = 0; i < 8; i++)
#pragma unroll
                for (int j = 0; j < 8; j++)
                    cr[i][j] += ar[i] * br[j];
        }
        __syncthreads();
    }

#pragma unroll
    for (int i = 0; i < 8; i++) {
        int m = mBase + ((i < 4) ? (tr * 4 + i) : (64 + tr * 4 + (i - 4)));
#pragma unroll
        for (int jh = 0; jh < 2; jh++) {
            int n = nBase + ((jh == 0) ? (tc * 4) : (64 + tc * 4));
            float4 vv;
            vv.x = cr[i][jh * 4 + 0];
            vv.y = cr[i][jh * 4 + 1];
            vv.z = cr[i][jh * 4 + 2];
            vv.w = cr[i][jh * 4 + 3];
            float* dst = &Ob[(size_t)m * N + n];
            if (accflag) {
                float4 o = *reinterpret_cast<const float4*>(dst);
                vv.x += o.x; vv.y += o.y; vv.z += o.z; vv.w += o.w;
            }
            *reinterpret_cast<float4*>(dst) = vv;
        }
    }
}

// ---------------------------------------------------------------------------
// Depthwise 3x3, SAME (zero) padding. One block = 32-row strip of one (b,c)
// plane; strip + 1-row halo staged through shared memory.
// grid = (4 strips, 1536 planes), block = 256
// ---------------------------------------------------------------------------
__global__ __launch_bounds__(256) void dw3x3_k(
    const float* __restrict__ in, const float* __restrict__ wdw,
    float* __restrict__ out)
{
    __shared__ float s[34 * 128];
    const int plane = blockIdx.y;
    const int c = plane % CDIM;
    const int y0 = blockIdx.x * 32;
    const float* ip = in + (size_t)plane * HW;
    float*       op = out + (size_t)plane * HW;

    // load rows y0-1 .. y0+32 (34 rows) as float4, zero-fill out-of-range rows
    for (int i = threadIdx.x; i < 34 * 32; i += 256) {
        int r  = i >> 5;           // 0..33
        int xq = (i & 31) << 2;    // 0..124
        int y  = y0 - 1 + r;
        float4 v = make_float4(0.f, 0.f, 0.f, 0.f);
        if (y >= 0 && y < HDIM)
            v = *reinterpret_cast<const float4*>(&ip[y * WDIM + xq]);
        *reinterpret_cast<float4*>(&s[r * 128 + xq]) = v;
    }
    float w[9];
#pragma unroll
    for (int j = 0; j < 9; j++) w[j] = wdw[c * 9 + j];
    __syncthreads();

    for (int i = threadIdx.x; i < 32 * 128; i += 256) {
        int ry = i >> 7;          // 0..31 -> plane row y0+ry, shared row ry+1..ry+... (ry+dy)
        int x  = i & 127;
        float acc = 0.f;
#pragma unroll
        for (int dy = 0; dy < 3; dy++) {
#pragma unroll
            for (int dx = -1; dx <= 1; dx++) {
                int xx = x + dx;
                if (xx >= 0 && xx < WDIM)
                    acc += w[dy * 3 + (dx + 1)] * s[(ry + dy) * 128 + xx];
            }
        }
        op[(y0 + ry) * WDIM + x] = acc;
    }
}

// ---------------------------------------------------------------------------
// Row L2 norms of q (blockIdx.y=0) and k (blockIdx.y=1): 1536 rows x 16384.
// ---------------------------------------------------------------------------
__global__ __launch_bounds__(256) void rownorm_k(
    const float* __restrict__ q, const float* __restrict__ k,
    float* __restrict__ norms)
{
    const float* p = ((blockIdx.y == 0) ? q : k) + (size_t)blockIdx.x * HW;
    float s = 0.f;
    for (int i = threadIdx.x; i < HW / 4; i += 256) {
        float4 v = *reinterpret_cast<const float4*>(&p[i * 4]);
        s += v.x * v.x + v.y * v.y + v.z * v.z + v.w * v.w;
    }
#pragma unroll
    for (int o = 16; o; o >>= 1) s += __shfl_xor_sync(0xFFFFFFFFu, s, o);
    __shared__ float red[8];
    if ((threadIdx.x & 31) == 0) red[threadIdx.x >> 5] = s;
    __syncthreads();
    if (threadIdx.x == 0) {
        float t = 0.f;
#pragma unroll
        for (int i = 0; i < 8; i++) t += red[i];
        norms[blockIdx.y * NPLANE + blockIdx.x] = fmaxf(sqrtf(t), 1e-12f);
    }
}

// ---------------------------------------------------------------------------
// Gram: G[bh][c][d] = sum_n q[bh,c,n] * k[bh,d,n]. 16-way K split, each split
// writes its own partial slab (deterministic, no atomics).
// grid = (16 splits, 32 bh), block = 256, K-tile = 64 through shared.
// ---------------------------------------------------------------------------
__global__ __launch_bounds__(256) void gram_k(
    const float* __restrict__ q, const float* __restrict__ k,
    float* __restrict__ Gpart)
{
    __shared__ float sq[CH * 64];
    __shared__ float sk[CH * 64];
    const int bh = blockIdx.y;
    const size_t base = (size_t)bh * CH * HW;
    const float* qp = q + base;
    const float* kp = k + base;
    const int kstart = blockIdx.x * 1024;

    float acc[9];
#pragma unroll
    for (int i = 0; i < 9; i++) acc[i] = 0.f;

    for (int kt = kstart; kt < kstart + 1024; kt += 64) {
        for (int i = threadIdx.x; i < CH * 16; i += 256) {   // 768 float4 per tensor
            int r  = i >> 4;           // 0..47
            int xq = (i & 15) << 2;    // 0..60
            *reinterpret_cast<float4*>(&sq[r * 64 + xq]) =
                *reinterpret_cast<const float4*>(&qp[(size_t)r * HW + kt + xq]);
            *reinterpret_cast<float4*>(&sk[r * 64 + xq]) =
                *reinterpret_cast<const float4*>(&kp[(size_t)r * HW + kt + xq]);
        }
        __syncthreads();
#pragma unroll
        for (int pi = 0; pi < 9; pi++) {
            int p = threadIdx.x + pi * 256;   // 0..2303
            int c = p / CH;
            int d = p - c * CH;
            float a = 0.f;
#pragma unroll 8
            for (int t = 0; t < 64; t++)
                a += sq[c * 64 + t] * sk[d * 64 + t];
            acc[pi] += a;
        }
        __syncthreads();
    }

    float* Gp = Gpart + ((size_t)blockIdx.x * 32 + bh) * (CH * CH);
#pragma unroll
    for (int pi = 0; pi < 9; pi++)
        Gp[threadIdx.x + pi * 256] = acc[pi];
}

// ---------------------------------------------------------------------------
// Reduce partials, apply 1/(|q||k|) * temperature, softmax over d.
// One thread per (bh, c) row.
// ---------------------------------------------------------------------------
__global__ void softmax_k(
    const float* __restrict__ Gpart, const float* __restrict__ norms,
    const float* __restrict__ temp, float* __restrict__ attn)
{
    int row = blockIdx.x * blockDim.x + threadIdx.x;
    if (row >= NPLANE) return;
    int bh = row / CH;
    int c  = row - bh * CH;
    int h  = bh & 7;
    float nq = norms[row];
    float tv = temp[h];

    float vals[CH];
    float vmax = -3.4e38f;
#pragma unroll
    for (int d = 0; d < CH; d++) {
        float g = 0.f;
        for (int s = 0; s < 16; s++)
            g += Gpart[((size_t)s * 32 + bh) * (CH * CH) + c * CH + d];
        float nk = norms[NPLANE + bh * CH + d];
        float v = g / (nq * nk) * tv;
        vals[d] = v;
        vmax = fmaxf(vmax, v);
    }
    float sum = 0.f;
#pragma unroll
    for (int d = 0; d < CH; d++) {
        vals[d] = expf(vals[d] - vmax);
        sum += vals[d];
    }
    float inv = 1.f / sum;
#pragma unroll
    for (int d = 0; d < CH; d++)
        attn[(size_t)bh * (CH * CH) + c * CH + d] = vals[d] * inv;
}

// ---------------------------------------------------------------------------
// out[bh,c,n] = sum_d attn[bh,c,d] * v[bh,d,n].
// grid = (32 n-tiles of 512, 32 bh), block = 256, 2 columns/thread.
// ---------------------------------------------------------------------------
__global__ __launch_bounds__(256) void attnv_k(
    const float* __restrict__ attn, const float* __restrict__ v,
    float* __restrict__ out)
{
    __shared__ float sA[CH * CH];
    const int bh = blockIdx.y;
    const float* Ab = attn + (size_t)bh * (CH * CH);
    for (int i = threadIdx.x; i < CH * CH; i += 256) sA[i] = Ab[i];
    __syncthreads();

    const size_t base = (size_t)bh * CH * HW;
    const float* vp = v + base;
    float*       op = out + base;
    const int n0 = blockIdx.x * 512 + threadIdx.x;
    const int n1 = n0 + 256;

    float a0[CH], a1[CH];
#pragma unroll
    for (int cc = 0; cc < CH; cc++) { a0[cc] = 0.f; a1[cc] = 0.f; }

    for (int d = 0; d < CH; d++) {
        float v0 = vp[(size_t)d * HW + n0];
        float v1 = vp[(size_t)d * HW + n1];
#pragma unroll
        for (int cc = 0; cc < CH; cc++) {
            float a = sA[cc * CH + d];
            a0[cc] += a * v0;
            a1[cc] += a * v1;
        }
    }
#pragma unroll
    for (int cc = 0; cc < CH; cc++) {
        op[(size_t)cc * HW + n0] = a0[cc];
        op[(size_t)cc * HW + n1] = a1[cc];
    }
}

// ---------------------------------------------------------------------------
extern "C" void kernel_launch(void* const* d_in, const int* in_sizes, int n_in,
                              void* d_out, int out_size)
{
    const float* x       = (const float*)d_in[0];
    const float* t       = (const float*)d_in[1];
    const float* w_q     = (const float*)d_in[2];
    const float* w_q_dw  = (const float*)d_in[3];
    const float* w_qT    = (const float*)d_in[4];
    const float* w_qT_dw = (const float*)d_in[5];
    const float* w_qcat  = (const float*)d_in[6];
    const float* w_k     = (const float*)d_in[7];
    const float* w_k_dw  = (const float*)d_in[8];
    const float* w_v     = (const float*)d_in[9];
    const float* w_v_dw  = (const float*)d_in[10];
    const float* temp    = (const float*)d_in[11];
    float* out = (float*)d_out;

    float *bA, *bB, *bC, *bD, *nrm, *gp, *at;
    cudaGetSymbolAddress((void**)&bA, g_bufA);
    cudaGetSymbolAddress((void**)&bB, g_bufB);
    cudaGetSymbolAddress((void**)&bC, g_bufC);
    cudaGetSymbolAddress((void**)&bD, g_bufD);
    cudaGetSymbolAddress((void**)&nrm, g_norms);
    cudaGetSymbolAddress((void**)&gp, g_gpart);
    cudaGetSymbolAddress((void**)&at, g_attn);

    dim3 gGemm(HW / 128, CDIM / 128, BATCH);   // (128, 3, 4)
    dim3 gDw(4, NPLANE);                        // (4, 1536)
    dim3 gNorm(NPLANE, 2);
    dim3 gGram(16, 32);
    dim3 gAv(HW / 512, 32);

    // q branch: q1 = dw(pw(x, w_q))
    sgemm_k<<<gGemm, 256>>>(w_q, CDIM, x, bA, 0);
    dw3x3_k<<<gDw, 256>>>(bA, w_q_dw, bB);
    // qT branch: q2 = dw(pw(t, w_qT))
    sgemm_k<<<gGemm, 256>>>(w_qT, CDIM, t, bA, 0);
    dw3x3_k<<<gDw, 256>>>(bA, w_qT_dw, bC);
    // q = w_qcat @ concat(q1, q2)  (two passes: left half, then right half +=)
    sgemm_k<<<gGemm, 256>>>(w_qcat, 2 * CDIM, bB, bD, 0);
    sgemm_k<<<gGemm, 256>>>(w_qcat + CDIM, 2 * CDIM, bC, bD, 1);
    // k = dw(pw(x, w_k))
    sgemm_k<<<gGemm, 256>>>(w_k, CDIM, x, bA, 0);
    dw3x3_k<<<gDw, 256>>>(bA, w_k_dw, bB);
    // v = dw(pw(x, w_v))
    sgemm_k<<<gGemm, 256>>>(w_v, CDIM, x, bA, 0);
    dw3x3_k<<<gDw, 256>>>(bA, w_v_dw, bC);
    // norms of q (bD) and k (bB)
    rownorm_k<<<gNorm, 256>>>(bD, bB, nrm);
    // gram partials, then scale + softmax
    gram_k<<<gGram, 256>>>(bD, bB, gp);
    softmax_k<<<12, 128>>>(gp, nrm, temp, at);
    // out = attn @ v
    attnv_k<<<gAv, 256>>>(at, bC, out);
}

// round 3
// speedup vs baseline: 1.4574x; 1.4574x over previous
#include <cuda_runtime.h>
#include <cstdint>
#include <math.h>

#define BATCH 4
#define CDIM 384
#define HDIM 128
#define WDIM 128
#define HW 16384
#define HEADS 8
#define CH 48
#define NPLANE (BATCH*CDIM)
#define NELEM (BATCH*CDIM*HW)

// GEMM tiling
#define BM 128
#define BN 256
#define BKK 16
#define ASTR 20     // smem floats per A row (pad: banks 20r+c distinct)
#define BSTR 264    // smem floats per B row (pad: banks 8k+n distinct)

// ---------------- static device scratch (no cudaMalloc allowed) -------------
__device__ float g_bufA[NELEM];
__device__ float g_bufB[NELEM];
__device__ float g_bufC[NELEM];
__device__ float g_bufD[NELEM];
__device__ float g_QQ[2*NELEM];    // concat [b][768][HW]
__device__ float g_norms[2*NPLANE];
__device__ float g_gpart[16*32*CH*CH];
__device__ float g_attn[32*CH*CH];

// ---------------- helpers ---------------------------------------------------
__device__ __forceinline__ uint32_t smem_u32(const void* p){
    uint32_t a;
    asm("{ .reg .u64 t; cvta.to.shared.u64 t, %1; cvt.u32.u64 %0, t; }"
        : "=r"(a) : "l"(p));
    return a;
}
__device__ __forceinline__ void cp16(uint32_t s, const void* g){
    asm volatile("cp.async.cg.shared.global [%0], [%1], 16;" :: "r"(s), "l"(g));
}
__device__ __forceinline__ void cp_commit(){ asm volatile("cp.async.commit_group;"); }
template<int N> __device__ __forceinline__ void cp_wait(){
    asm volatile("cp.async.wait_group %0;" :: "n"(N));
}
__device__ __forceinline__ uint32_t f2tf32(float x){
    uint32_t u;
    asm("cvt.rna.tf32.f32 %0, %1;" : "=r"(u) : "f"(x));
    return u;
}
__device__ __forceinline__ void mma_tf32(float* c, uint32_t a0, uint32_t a1,
                                         uint32_t a2, uint32_t a3,
                                         uint32_t b0, uint32_t b1){
    asm volatile(
        "mma.sync.aligned.m16n8k8.row.col.f32.tf32.tf32.f32 "
        "{%0,%1,%2,%3}, {%4,%5,%6,%7}, {%8,%9}, {%0,%1,%2,%3};"
        : "+f"(c[0]), "+f"(c[1]), "+f"(c[2]), "+f"(c[3])
        : "r"(a0), "r"(a1), "r"(a2), "r"(a3), "r"(b0), "r"(b1));
}

// ---------------------------------------------------------------------------
// TF32 tensor-core GEMM: O[b] (384 x 16384) = A (384 x K) @ B[b] (K x 16384)
//   A row-major [384][lda], B per-batch [K][HW] (N contiguous), O [384][HW].
// Block 128x256, BK=16, 8 warps of 64x64, double-buffered cp.async.
// grid = (HW/256, 384/128, BATCH), block = 256.
// ---------------------------------------------------------------------------
__global__ __launch_bounds__(256, 1) void mmagemm_k(
    const float* __restrict__ A, int lda,
    const float* __restrict__ B, int K,
    float* __restrict__ O)
{
    extern __shared__ float sm[];
    float* sAb[2] = { sm, sm + BM*ASTR };
    float* sBb[2] = { sm + 2*BM*ASTR, sm + 2*BM*ASTR + BKK*BSTR };

    const int tid  = threadIdx.x;
    const int wid  = tid >> 5;
    const int lane = tid & 31;
    const int wm = (wid & 1) * 64;      // warp M offset in tile
    const int wn = (wid >> 1) * 32 * 2; // warp N offset (4 warps * 64)

    const int mBase = blockIdx.y * BM;
    const int nBase = blockIdx.x * BN;
    const float* Ag = A + (size_t)mBase * lda;
    const float* Bg = B + (size_t)blockIdx.z * K * HW + nBase;
    float* Ob = O + (size_t)blockIdx.z * CDIM * HW + (size_t)mBase * HW + nBase;

    float acc[4][8][4];
#pragma unroll
    for (int i = 0; i < 4; i++)
#pragma unroll
        for (int j = 0; j < 8; j++)
#pragma unroll
            for (int r = 0; r < 4; r++) acc[i][j][r] = 0.f;

    const int nk = K / BKK;

    auto load_tile = [&](int kt, int buf){
        float* sA = sAb[buf];
        float* sB = sBb[buf];
        const int k0 = kt * BKK;
#pragma unroll
        for (int i = 0; i < 2; i++){             // A: 128 x 16 = 512 float4
            int f = tid + i * 256;
            int row = f >> 2;
            int q   = (f & 3) << 2;
            cp16(smem_u32(&sA[row * ASTR + q]), Ag + (size_t)row * lda + k0 + q);
        }
#pragma unroll
        for (int i = 0; i < 4; i++){             // B: 16 x 256 = 1024 float4
            int f = tid + i * 256;
            int kr = f >> 6;
            int nq = (f & 63) << 2;
            cp16(smem_u32(&sB[kr * BSTR + nq]), Bg + (size_t)(k0 + kr) * HW + nq);
        }
        cp_commit();
    };

    load_tile(0, 0);
    int buf = 0;

    for (int kt = 0; kt < nk; kt++){
        cp_wait<0>();
        __syncthreads();
        if (kt + 1 < nk) load_tile(kt + 1, buf ^ 1);

        const float* sA = sAb[buf];
        const float* sB = sBb[buf];
        const int r = lane >> 2;
        const int cq = lane & 3;

#pragma unroll
        for (int ks = 0; ks < 2; ks++){
            const int k0 = ks * 8;
            uint32_t af[4][4];
#pragma unroll
            for (int mt = 0; mt < 4; mt++){
                const float* ap = &sA[(wm + mt * 16 + r) * ASTR + k0 + cq];
                af[mt][0] = f2tf32(ap[0]);
                af[mt][2] = f2tf32(ap[4]);
                const float* ap2 = ap + 8 * ASTR;
                af[mt][1] = f2tf32(ap2[0]);
                af[mt][3] = f2tf32(ap2[4]);
            }
            uint32_t bf[8][2];
#pragma unroll
            for (int nt = 0; nt < 8; nt++){
                const float* bp = &sB[(k0 + cq) * BSTR + wn + nt * 8 + r];
                bf[nt][0] = f2tf32(bp[0]);
                bf[nt][1] = f2tf32(bp[4 * BSTR]);
            }
#pragma unroll
            for (int mt = 0; mt < 4; mt++)
#pragma unroll
                for (int nt = 0; nt < 8; nt++)
                    mma_tf32(acc[mt][nt], af[mt][0], af[mt][1], af[mt][2],
                             af[mt][3], bf[nt][0], bf[nt][1]);
        }
        __syncthreads();
        buf ^= 1;
    }

    // epilogue: c0,c1 -> (row, 2c), (row, 2c+1); c2,c3 -> row+8
    const int r = lane >> 2;
    const int c2 = (lane & 3) * 2;
#pragma unroll
    for (int mt = 0; mt < 4; mt++){
        int row0 = wm + mt * 16 + r;
#pragma unroll
        for (int nt = 0; nt < 8; nt++){
            int col = wn + nt * 8 + c2;
            float2 v0 = make_float2(acc[mt][nt][0], acc[mt][nt][1]);
            float2 v1 = make_float2(acc[mt][nt][2], acc[mt][nt][3]);
            *reinterpret_cast<float2*>(&Ob[(size_t)row0 * HW + col]) = v0;
            *reinterpret_cast<float2*>(&Ob[(size_t)(row0 + 8) * HW + col]) = v1;
        }
    }
}

// ---------------------------------------------------------------------------
// Depthwise 3x3 SAME; output goes to [b][opb][HW] at channel offset coff.
// grid = (4 strips, 1536 planes), block = 256
// ---------------------------------------------------------------------------
__global__ __launch_bounds__(256) void dw3x3_k(
    const float* __restrict__ in, const float* __restrict__ wdw,
    float* __restrict__ out, int opb, int coff)
{
    __shared__ float s[34 * 128];
    const int plane = blockIdx.y;
    const int b = plane / CDIM;
    const int c = plane % CDIM;
    const int y0 = blockIdx.x * 32;
    const float* ip = in + (size_t)plane * HW;
    float*       op = out + ((size_t)b * opb + coff + c) * HW;

    for (int i = threadIdx.x; i < 34 * 32; i += 256) {
        int r  = i >> 5;
        int xq = (i & 31) << 2;
        int y  = y0 - 1 + r;
        float4 v = make_float4(0.f, 0.f, 0.f, 0.f);
        if (y >= 0 && y < HDIM)
            v = *reinterpret_cast<const float4*>(&ip[y * WDIM + xq]);
        *reinterpret_cast<float4*>(&s[r * 128 + xq]) = v;
    }
    float w[9];
#pragma unroll
    for (int j = 0; j < 9; j++) w[j] = wdw[c * 9 + j];
    __syncthreads();

    for (int i = threadIdx.x; i < 32 * 128; i += 256) {
        int ry = i >> 7;
        int x  = i & 127;
        float acc = 0.f;
#pragma unroll
        for (int dy = 0; dy < 3; dy++) {
#pragma unroll
            for (int dx = -1; dx <= 1; dx++) {
                int xx = x + dx;
                if (xx >= 0 && xx < WDIM)
                    acc += w[dy * 3 + (dx + 1)] * s[(ry + dy) * 128 + xx];
            }
        }
        op[(y0 + ry) * WDIM + x] = acc;
    }
}

// ---------------------------------------------------------------------------
__global__ __launch_bounds__(256) void rownorm_k(
    const float* __restrict__ q, const float* __restrict__ k,
    float* __restrict__ norms)
{
    const float* p = ((blockIdx.y == 0) ? q : k) + (size_t)blockIdx.x * HW;
    float s = 0.f;
    for (int i = threadIdx.x; i < HW / 4; i += 256) {
        float4 v = *reinterpret_cast<const float4*>(&p[i * 4]);
        s += v.x * v.x + v.y * v.y + v.z * v.z + v.w * v.w;
    }
#pragma unroll
    for (int o = 16; o; o >>= 1) s += __shfl_xor_sync(0xFFFFFFFFu, s, o);
    __shared__ float red[8];
    if ((threadIdx.x & 31) == 0) red[threadIdx.x >> 5] = s;
    __syncthreads();
    if (threadIdx.x == 0) {
        float t = 0.f;
#pragma unroll
        for (int i = 0; i < 8; i++) t += red[i];
        norms[blockIdx.y * NPLANE + blockIdx.x] = fmaxf(sqrtf(t), 1e-12f);
    }
}

// ---------------------------------------------------------------------------
__global__ __launch_bounds__(256) void gram_k(
    const float* __restrict__ q, const float* __restrict__ k,
    float* __restrict__ Gpart)
{
    __shared__ float sq[CH * 64];
    __shared__ float sk[CH * 64];
    const int bh = blockIdx.y;
    const size_t base = (size_t)bh * CH * HW;
    const float* qp = q + base;
    const float* kp = k + base;
    const int kstart = blockIdx.x * 1024;

    float acc[9];
#pragma unroll
    for (int i = 0; i < 9; i++) acc[i] = 0.f;

    for (int kt = kstart; kt < kstart + 1024; kt += 64) {
        for (int i = threadIdx.x; i < CH * 16; i += 256) {
            int r  = i >> 4;
            int xq = (i & 15) << 2;
            *reinterpret_cast<float4*>(&sq[r * 64 + xq]) =
                *reinterpret_cast<const float4*>(&qp[(size_t)r * HW + kt + xq]);
            *reinterpret_cast<float4*>(&sk[r * 64 + xq]) =
                *reinterpret_cast<const float4*>(&kp[(size_t)r * HW + kt + xq]);
        }
        __syncthreads();
#pragma unroll
        for (int pi = 0; pi < 9; pi++) {
            int p = threadIdx.x + pi * 256;
            int c = p / CH;
            int d = p - c * CH;
            float a = 0.f;
#pragma unroll 8
            for (int t = 0; t < 64; t++)
                a += sq[c * 64 + t] * sk[d * 64 + t];
            acc[pi] += a;
        }
        __syncthreads();
    }

    float* Gp = Gpart + ((size_t)blockIdx.x * 32 + bh) * (CH * CH);
#pragma unroll
    for (int pi = 0; pi < 9; pi++)
        Gp[threadIdx.x + pi * 256] = acc[pi];
}

// ---------------------------------------------------------------------------
__global__ void softmax_k(
    const float* __restrict__ Gpart, const float* __restrict__ norms,
    const float* __restrict__ temp, float* __restrict__ attn)
{
    int row = blockIdx.x * blockDim.x + threadIdx.x;
    if (row >= NPLANE) return;
    int bh = row / CH;
    int c  = row - bh * CH;
    int h  = bh & 7;
    float nq = norms[row];
    float tv = temp[h];

    float vals[CH];
    float vmax = -3.4e38f;
#pragma unroll
    for (int d = 0; d < CH; d++) {
        float g = 0.f;
        for (int s = 0; s < 16; s++)
            g += Gpart[((size_t)s * 32 + bh) * (CH * CH) + c * CH + d];
        float nk = norms[NPLANE + bh * CH + d];
        float v = g / (nq * nk) * tv;
        vals[d] = v;
        vmax = fmaxf(vmax, v);
    }
    float sum = 0.f;
#pragma unroll
    for (int d = 0; d < CH; d++) {
        vals[d] = expf(vals[d] - vmax);
        sum += vals[d];
    }
    float inv = 1.f / sum;
#pragma unroll
    for (int d = 0; d < CH; d++)
        attn[(size_t)bh * (CH * CH) + c * CH + d] = vals[d] * inv;
}

// ---------------------------------------------------------------------------
__global__ __launch_bounds__(256) void attnv_k(
    const float* __restrict__ attn, const float* __restrict__ v,
    float* __restrict__ out)
{
    __shared__ float sA[CH * CH];
    const int bh = blockIdx.y;
    const float* Ab = attn + (size_t)bh * (CH * CH);
    for (int i = threadIdx.x; i < CH * CH; i += 256) sA[i] = Ab[i];
    __syncthreads();

    const size_t base = (size_t)bh * CH * HW;
    const float* vp = v + base;
    float*       op = out + base;
    const int n0 = blockIdx.x * 512 + threadIdx.x;
    const int n1 = n0 + 256;

    float a0[CH], a1[CH];
#pragma unroll
    for (int cc = 0; cc < CH; cc++) { a0[cc] = 0.f; a1[cc] = 0.f; }

    for (int d = 0; d < CH; d++) {
        float v0 = vp[(size_t)d * HW + n0];
        float v1 = vp[(size_t)d * HW + n1];
#pragma unroll
        for (int cc = 0; cc < CH; cc++) {
            float a = sA[cc * CH + d];
            a0[cc] += a * v0;
            a1[cc] += a * v1;
        }
    }
#pragma unroll
    for (int cc = 0; cc < CH; cc++) {
        op[(size_t)cc * HW + n0] = a0[cc];
        op[(size_t)cc * HW + n1] = a1[cc];
    }
}

// ---------------------------------------------------------------------------
extern "C" void kernel_launch(void* const* d_in, const int* in_sizes, int n_in,
                              void* d_out, int out_size)
{
    const float* x       = (const float*)d_in[0];
    const float* t       = (const float*)d_in[1];
    const float* w_q     = (const float*)d_in[2];
    const float* w_q_dw  = (const float*)d_in[3];
    const float* w_qT    = (const float*)d_in[4];
    const float* w_qT_dw = (const float*)d_in[5];
    const float* w_qcat  = (const float*)d_in[6];
    const float* w_k     = (const float*)d_in[7];
    const float* w_k_dw  = (const float*)d_in[8];
    const float* w_v     = (const float*)d_in[9];
    const float* w_v_dw  = (const float*)d_in[10];
    const float* temp    = (const float*)d_in[11];
    float* out = (float*)d_out;

    float *bA, *bB, *bC, *bD, *qq, *nrm, *gp, *at;
    cudaGetSymbolAddress((void**)&bA, g_bufA);
    cudaGetSymbolAddress((void**)&bB, g_bufB);
    cudaGetSymbolAddress((void**)&bC, g_bufC);
    cudaGetSymbolAddress((void**)&bD, g_bufD);
    cudaGetSymbolAddress((void**)&qq, g_QQ);
    cudaGetSymbolAddress((void**)&nrm, g_norms);
    cudaGetSymbolAddress((void**)&gp, g_gpart);
    cudaGetSymbolAddress((void**)&at, g_attn);

    const int SMEMSZ = (2 * BM * ASTR + 2 * BKK * BSTR) * 4;  // 54272 B
    static int s_attr_done = 0;
    if (!s_attr_done) {
        cudaFuncSetAttribute(mmagemm_k,
                             cudaFuncAttributeMaxDynamicSharedMemorySize, SMEMSZ);
        s_attr_done = 1;
    }

    dim3 gG(HW / BN, CDIM / BM, BATCH);   // (64, 3, 4)
    dim3 gDw(4, NPLANE);
    dim3 gNorm(NPLANE, 2);
    dim3 gGram(16, 32);
    dim3 gAv(HW / 512, 32);

    // q1 = dw(pw(x, w_q)) -> qq[:, 0:384]
    mmagemm_k<<<gG, 256, SMEMSZ>>>(w_q, CDIM, x, CDIM, bA);
    dw3x3_k<<<gDw, 256>>>(bA, w_q_dw, qq, 2 * CDIM, 0);
    // q2 = dw(pw(t, w_qT)) -> qq[:, 384:768]
    mmagemm_k<<<gG, 256, SMEMSZ>>>(w_qT, CDIM, t, CDIM, bA);
    dw3x3_k<<<gDw, 256>>>(bA, w_qT_dw, qq, 2 * CDIM, CDIM);
    // q = w_qcat @ concat  (single K=768 GEMM)
    mmagemm_k<<<gG, 256, SMEMSZ>>>(w_qcat, 2 * CDIM, qq, 2 * CDIM, bD);
    // k, v
    mmagemm_k<<<gG, 256, SMEMSZ>>>(w_k, CDIM, x, CDIM, bA);
    dw3x3_k<<<gDw, 256>>>(bA, w_k_dw, bB, CDIM, 0);
    mmagemm_k<<<gG, 256, SMEMSZ>>>(w_v, CDIM, x, CDIM, bA);
    dw3x3_k<<<gDw, 256>>>(bA, w_v_dw, bC, CDIM, 0);

    // attention tail (fp32)
    rownorm_k<<<gNorm, 256>>>(bD, bB, nrm);
    gram_k<<<gGram, 256>>>(bD, bB, gp);
    softmax_k<<<12, 128>>>(gp, nrm, temp, at);
    attnv_k<<<gAv, 256>>>(at, bC, out);
}